// round 1
// baseline (speedup 1.0000x reference)
#include <cuda_runtime.h>
#include <cuda_bf16.h>
#include <cstdint>

#define N_NODES 50000
#define N_EDGES 800000
#define HDIM    128
#define N_RELS  24

// ---------------- scratch (device globals; no allocation allowed) ----------------
__device__ float g_Hr[(size_t)N_RELS * N_NODES * HDIM];   // 614.4 MB
__device__ float g_self[(size_t)N_NODES * HDIM];          // 25.6 MB
__device__ int   g_deg[N_NODES];
__device__ int   g_cursor[N_NODES];
__device__ int   g_off[N_NODES + 1];
__device__ int   g_ekey[N_EDGES];                         // (rel<<16)|src, grouped by dst

// ---------------- degree histogram ----------------
__global__ void k_deg(const int* __restrict__ dst) {
    int i = blockIdx.x * blockDim.x + threadIdx.x;
    if (i < N_EDGES) atomicAdd(&g_deg[dst[i]], 1);
}

// ---------------- single-block exclusive scan over g_deg -> g_off ----------------
__global__ void k_scan() {
    __shared__ int sbuf[1024];
    __shared__ int s_carry;
    int tid = threadIdx.x;
    if (tid == 0) s_carry = 0;
    __syncthreads();
    const int CH = 8192;   // 1024 threads * 8
    for (int base = 0; base < N_NODES; base += CH) {
        int idx0 = base + tid * 8;
        int v[8];
        int s = 0;
#pragma unroll
        for (int j = 0; j < 8; j++) {
            v[j] = (idx0 + j < N_NODES) ? g_deg[idx0 + j] : 0;
            s += v[j];
        }
        sbuf[tid] = s;
        __syncthreads();
        for (int off = 1; off < 1024; off <<= 1) {
            int t2 = (tid >= off) ? sbuf[tid - off] : 0;
            __syncthreads();
            sbuf[tid] += t2;
            __syncthreads();
        }
        int excl = s_carry + sbuf[tid] - s;
#pragma unroll
        for (int j = 0; j < 8; j++) {
            if (idx0 + j < N_NODES) g_off[idx0 + j] = excl;
            excl += v[j];
        }
        __syncthreads();
        if (tid == 1023) s_carry += sbuf[1023];
        __syncthreads();
    }
    if (tid == 0) g_off[N_NODES] = s_carry;
}

// ---------------- scatter edges into CSR-by-dst ----------------
__global__ void k_scatter(const int* __restrict__ src, const int* __restrict__ dst,
                          const int* __restrict__ rel) {
    int i = blockIdx.x * blockDim.x + threadIdx.x;
    if (i < N_EDGES) {
        int d = dst[i];
        int p = g_off[d] + atomicAdd(&g_cursor[d], 1);
        g_ekey[p] = (rel[i] << 16) | src[i];
    }
}

// ---------------- batched GEMM: Hr[r] = h @ W[r]; r==N_RELS -> self = h @ W_loop --
// 128x128 tile (full K=D=128 in one pass), 256 threads, 8x8 microtile.
__global__ __launch_bounds__(256, 1)
void k_gemm(const float* __restrict__ h, const float* __restrict__ W,
            const float* __restrict__ W_loop) {
    extern __shared__ float smem[];
    float* As = smem;                 // [128][128] row-major (row, k)
    float* Bs = smem + 128 * 128;     // [128][128] (k, j)

    const int r  = blockIdx.y;
    const float* Wp   = (r < N_RELS) ? (W + (size_t)r * HDIM * HDIM) : W_loop;
    float*       outp = (r < N_RELS) ? (g_Hr + (size_t)r * N_NODES * HDIM) : g_self;
    const int m0 = blockIdx.x * 128;
    const int t  = threadIdx.x;

    // load W tile (16384 floats = 4096 float4)
    for (int q = t; q < 4096; q += 256)
        ((float4*)Bs)[q] = ((const float4*)Wp)[q];
    // load h tile (guard tail rows with zeros)
    for (int q = t; q < 4096; q += 256) {
        int row = q >> 5;          // 32 float4 per row
        int c4  = q & 31;
        float4 v = make_float4(0.f, 0.f, 0.f, 0.f);
        if (m0 + row < N_NODES)
            v = ((const float4*)(h + (size_t)(m0 + row) * HDIM))[c4];
        ((float4*)As)[q] = v;
    }
    __syncthreads();

    const int ty = t >> 4, tx = t & 15;
    const int i0 = ty * 8, j0 = tx * 8;

    float acc[8][8];
#pragma unroll
    for (int a = 0; a < 8; a++)
#pragma unroll
        for (int b = 0; b < 8; b++) acc[a][b] = 0.f;

    const float* Arow = As + i0 * HDIM;

#pragma unroll 4
    for (int k = 0; k < HDIM; ++k) {
        float a[8];
#pragma unroll
        for (int ii = 0; ii < 8; ii++) a[ii] = Arow[ii * HDIM + k];
        float4 b0 = *(const float4*)(Bs + k * HDIM + j0);
        float4 b1 = *(const float4*)(Bs + k * HDIM + j0 + 4);
        float bb[8] = {b0.x, b0.y, b0.z, b0.w, b1.x, b1.y, b1.z, b1.w};
#pragma unroll
        for (int ii = 0; ii < 8; ii++)
#pragma unroll
            for (int jj = 0; jj < 8; jj++)
                acc[ii][jj] = fmaf(a[ii], bb[jj], acc[ii][jj]);
    }

#pragma unroll
    for (int ii = 0; ii < 8; ii++) {
        int row = m0 + i0 + ii;
        if (row < N_NODES) {
            float4 o0 = make_float4(acc[ii][0], acc[ii][1], acc[ii][2], acc[ii][3]);
            float4 o1 = make_float4(acc[ii][4], acc[ii][5], acc[ii][6], acc[ii][7]);
            *(float4*)(outp + (size_t)row * HDIM + j0)     = o0;
            *(float4*)(outp + (size_t)row * HDIM + j0 + 4) = o1;
        }
    }
}

// ---------------- aggregation: warp per node; fuse mean + self-loop + bias + relu -
__global__ void k_aggregate(const float* __restrict__ bias, float* __restrict__ out) {
    int warp = (blockIdx.x * blockDim.x + threadIdx.x) >> 5;
    int lane = threadIdx.x & 31;
    if (warp >= N_NODES) return;
    int beg = g_off[warp], end = g_off[warp + 1];
    float4 acc = make_float4(0.f, 0.f, 0.f, 0.f);
    int e = beg;
    for (; e + 1 < end; e += 2) {
        int k0 = g_ekey[e], k1 = g_ekey[e + 1];
        const float4* p0 = (const float4*)(g_Hr + ((size_t)(k0 >> 16) * N_NODES + (k0 & 0xFFFF)) * HDIM);
        const float4* p1 = (const float4*)(g_Hr + ((size_t)(k1 >> 16) * N_NODES + (k1 & 0xFFFF)) * HDIM);
        float4 m0 = p0[lane];
        float4 m1 = p1[lane];
        acc.x += m0.x + m1.x; acc.y += m0.y + m1.y;
        acc.z += m0.z + m1.z; acc.w += m0.w + m1.w;
    }
    if (e < end) {
        int k0 = g_ekey[e];
        const float4* p0 = (const float4*)(g_Hr + ((size_t)(k0 >> 16) * N_NODES + (k0 & 0xFFFF)) * HDIM);
        float4 m0 = p0[lane];
        acc.x += m0.x; acc.y += m0.y; acc.z += m0.z; acc.w += m0.w;
    }
    float scale = (end > beg) ? (1.0f / (float)(end - beg)) : 0.0f;
    float4 s = ((const float4*)(g_self + (size_t)warp * HDIM))[lane];
    float4 b = ((const float4*)bias)[lane];
    float4 o;
    o.x = fmaxf(fmaf(acc.x, scale, s.x + b.x), 0.f);
    o.y = fmaxf(fmaf(acc.y, scale, s.y + b.y), 0.f);
    o.z = fmaxf(fmaf(acc.z, scale, s.z + b.z), 0.f);
    o.w = fmaxf(fmaf(acc.w, scale, s.w + b.w), 0.f);
    ((float4*)out)[(size_t)warp * 32 + lane] = o;
}

// ---------------- launch ----------------
extern "C" void kernel_launch(void* const* d_in, const int* in_sizes, int n_in,
                              void* d_out, int out_size) {
    const float* h      = (const float*)d_in[0];
    const float* W      = (const float*)d_in[1];
    const float* W_loop = (const float*)d_in[2];
    const float* bias   = (const float*)d_in[3];
    const int*   src    = (const int*)d_in[4];
    const int*   dst    = (const int*)d_in[5];
    const int*   rel    = (const int*)d_in[6];
    float* out = (float*)d_out;

    void* p_deg = nullptr;
    void* p_cur = nullptr;
    cudaGetSymbolAddress(&p_deg, g_deg);
    cudaGetSymbolAddress(&p_cur, g_cursor);
    cudaMemsetAsync(p_deg, 0, N_NODES * sizeof(int));
    cudaMemsetAsync(p_cur, 0, N_NODES * sizeof(int));

    cudaFuncSetAttribute(k_gemm, cudaFuncAttributeMaxDynamicSharedMemorySize, 131072);

    const int EB = (N_EDGES + 255) / 256;
    k_deg<<<EB, 256>>>(dst);
    k_scan<<<1, 1024>>>();
    k_scatter<<<EB, 256>>>(src, dst, rel);

    dim3 ggrid((N_NODES + 127) / 128, N_RELS + 1);
    k_gemm<<<ggrid, 256, 131072>>>(h, W, W_loop);

    int agg_blocks = (N_NODES * 32 + 255) / 256;
    k_aggregate<<<agg_blocks, 256>>>(bias, out);
}

// round 3
// speedup vs baseline: 2.5709x; 2.5709x over previous
#include <cuda_runtime.h>
#include <cuda_bf16.h>
#include <cstdint>

#define N_NODES 50000
#define N_EDGES 800000
#define HDIM    128
#define N_RELS  24
#define M_TILES 391          /* ceil(50000/128) */
#define NMAT    25           /* 24 relations + self-loop */

// ---------------- scratch (device globals; no allocation allowed) ----------------
__device__ float g_Hr[(size_t)N_RELS * N_NODES * HDIM];   // 614.4 MB
__device__ float g_self[(size_t)N_NODES * HDIM];          // 25.6 MB
__device__ int   g_deg[N_NODES];
__device__ int   g_cursor[N_NODES];
__device__ int   g_off[N_NODES + 1];
__device__ int   g_ekey[N_EDGES];                         // (rel<<16)|src, grouped by dst

// W^T split into bf16 hi/lo, plain (n,k) row-major per matrix (k contiguous)
__device__ __nv_bfloat16 g_Bhi[(size_t)NMAT * HDIM * HDIM];   // 0.8 MB
__device__ __nv_bfloat16 g_Blo[(size_t)NMAT * HDIM * HDIM];

// ---------------- smem layout for GEMM (padded rows: 272 B = 136 bf16) ----------
#define ROWB    272
#define TILE_B  (128 * ROWB)            /* 34816 bytes per 128x128 bf16 tile */
#define SA_HI   0
#define SA_LO   TILE_B
#define SB_BASE (2 * TILE_B)
#define SM_TOTAL (6 * TILE_B)           /* A hi/lo + 2 B bufs (hi/lo each) = 208896 */

// ================= helpers =================
#define CP_COMMIT()  asm volatile("cp.async.commit_group;" ::: "memory")

__device__ __forceinline__ void cp16s(void* dst_smem, const void* src) {
    uint32_t d;
    asm("{ .reg .u64 t; cvta.to.shared.u64 t, %1; cvt.u32.u64 %0, t; }" : "=r"(d) : "l"(dst_smem));
    asm volatile("cp.async.cg.shared.global [%0], [%1], 16;" :: "r"(d), "l"(src));
}

__device__ __forceinline__ void mma16816(float* c, const uint32_t* a, const uint32_t* b) {
    asm volatile(
        "mma.sync.aligned.m16n8k16.row.col.f32.bf16.bf16.f32 "
        "{%0,%1,%2,%3}, {%4,%5,%6,%7}, {%8,%9}, {%0,%1,%2,%3};"
        : "+f"(c[0]), "+f"(c[1]), "+f"(c[2]), "+f"(c[3])
        : "r"(a[0]), "r"(a[1]), "r"(a[2]), "r"(a[3]), "r"(b[0]), "r"(b[1]));
}

// split 4 floats -> packed bf16 hi pair-of-2 and lo pair-of-2
__device__ __forceinline__ void split4(const float4 v, uint2& uhi, uint2& ulo) {
    float f[4] = {v.x, v.y, v.z, v.w};
    unsigned short hb[4], lb[4];
#pragma unroll
    for (int j = 0; j < 4; j++) {
        __nv_bfloat16 hi = __float2bfloat16(f[j]);
        float hf = __bfloat162float(hi);
        __nv_bfloat16 lo = __float2bfloat16(f[j] - hf);
        hb[j] = *reinterpret_cast<unsigned short*>(&hi);
        lb[j] = *reinterpret_cast<unsigned short*>(&lo);
    }
    uhi = make_uint2((uint32_t)hb[0] | ((uint32_t)hb[1] << 16), (uint32_t)hb[2] | ((uint32_t)hb[3] << 16));
    ulo = make_uint2((uint32_t)lb[0] | ((uint32_t)lb[1] << 16), (uint32_t)lb[2] | ((uint32_t)lb[3] << 16));
}

// ---------------- conv B: g_B[r][n][k] = split(W[r][k][n]) ----------------------
__global__ void k_convB(const float* __restrict__ W, const float* __restrict__ W_loop) {
    int idx = blockIdx.x * blockDim.x + threadIdx.x;
    if (idx >= NMAT * 4096) return;
    int r = idx >> 12, q = idx & 4095;
    int n = q >> 5, c4 = q & 31;          // k = c4*4 .. c4*4+3
    const float* Wsrc = (r < N_RELS) ? (W + (size_t)r * HDIM * HDIM) : W_loop;
    float4 v;
    v.x = Wsrc[(size_t)(c4 * 4 + 0) * HDIM + n];
    v.y = Wsrc[(size_t)(c4 * 4 + 1) * HDIM + n];
    v.z = Wsrc[(size_t)(c4 * 4 + 2) * HDIM + n];
    v.w = Wsrc[(size_t)(c4 * 4 + 3) * HDIM + n];
    uint2 uhi, ulo;
    split4(v, uhi, ulo);
    size_t off = (size_t)r * HDIM * HDIM + (size_t)n * HDIM + c4 * 4;
    *(uint2*)(g_Bhi + off) = uhi;
    *(uint2*)(g_Blo + off) = ulo;
}

// ---------------- GEMM via mma.sync: CTA = one 128-row tile, loops 25 matrices ---
__global__ __launch_bounds__(256, 1) void k_gemm_mma(const float* __restrict__ h) {
    extern __shared__ char smem[];
    const int tid = threadIdx.x;
    const int m0 = blockIdx.x * 128;

    // ---- prologue: load + split-convert A tile into smem (padded rows) ----
    for (int q = tid; q < 4096; q += 256) {
        int row = q >> 5, c4 = q & 31;
        float4 v = make_float4(0.f, 0.f, 0.f, 0.f);
        int grow = m0 + row;
        if (grow < N_NODES) v = ((const float4*)(h + (size_t)grow * HDIM))[c4];
        uint2 uhi, ulo;
        split4(v, uhi, ulo);
        *(uint2*)(smem + SA_HI + row * ROWB + c4 * 8) = uhi;
        *(uint2*)(smem + SA_LO + row * ROWB + c4 * 8) = ulo;
    }

    // ---- B prefetch helper (hi+lo -> buffer buf) ----
    auto issue_B = [&](int r, int buf) {
        char* bh = smem + SB_BASE + buf * (2 * TILE_B);
        char* bl = bh + TILE_B;
        const char* gh = (const char*)g_Bhi + (size_t)r * 32768;
        const char* gl = (const char*)g_Blo + (size_t)r * 32768;
        for (int q = tid; q < 2048; q += 256) {
            int row = q >> 4, seg = q & 15;
            cp16s(bh + row * ROWB + seg * 16, gh + row * 256 + seg * 16);
            cp16s(bl + row * ROWB + seg * 16, gl + row * 256 + seg * 16);
        }
    };

    issue_B(0, 0);
    CP_COMMIT();

    const int lane = tid & 31, wid = tid >> 5;
    const int g = lane >> 2, t = lane & 3;
    const int wm = (wid & 1) * 64;        // warp m offset
    const int wn = (wid >> 1) * 32;       // warp n offset

    for (int r = 0; r < NMAT; r++) {
        if (r + 1 < NMAT) {
            issue_B(r + 1, (r + 1) & 1);
            CP_COMMIT();
            asm volatile("cp.async.wait_group 1;" ::: "memory");
        } else {
            asm volatile("cp.async.wait_group 0;" ::: "memory");
        }
        __syncthreads();

        const char* Bh = smem + SB_BASE + (r & 1) * (2 * TILE_B);
        const char* Bl = Bh + TILE_B;
        const char* Ah = smem + SA_HI;
        const char* Al = smem + SA_LO;

        float acc[4][4][4];
#pragma unroll
        for (int mi = 0; mi < 4; mi++)
#pragma unroll
            for (int ni = 0; ni < 4; ni++)
#pragma unroll
                for (int c = 0; c < 4; c++) acc[mi][ni][c] = 0.f;

#pragma unroll
        for (int p = 0; p < 3; p++) {
            const char* A = (p == 2) ? Al : Ah;
            const char* B = (p == 1) ? Bl : Bh;
#pragma unroll
            for (int ks = 0; ks < 8; ks++) {
                const int kb = ks * 32 + t * 4;
                uint32_t a[4][4];
#pragma unroll
                for (int mi = 0; mi < 4; mi++) {
                    const char* base = A + (wm + mi * 16 + g) * ROWB + kb;
                    a[mi][0] = *(const uint32_t*)(base);
                    a[mi][1] = *(const uint32_t*)(base + 8 * ROWB);
                    a[mi][2] = *(const uint32_t*)(base + 16);
                    a[mi][3] = *(const uint32_t*)(base + 8 * ROWB + 16);
                }
                uint32_t b[4][2];
#pragma unroll
                for (int ni = 0; ni < 4; ni++) {
                    const char* base = B + (wn + ni * 8 + g) * ROWB + kb;
                    b[ni][0] = *(const uint32_t*)(base);
                    b[ni][1] = *(const uint32_t*)(base + 16);
                }
#pragma unroll
                for (int mi = 0; mi < 4; mi++)
#pragma unroll
                    for (int ni = 0; ni < 4; ni++)
                        mma16816(acc[mi][ni], a[mi], b[ni]);
            }
        }

        // ---- store D tile ----
        float* outp = (r < N_RELS) ? (g_Hr + (size_t)r * N_NODES * HDIM) : g_self;
#pragma unroll
        for (int mi = 0; mi < 4; mi++) {
            int row0 = m0 + wm + mi * 16 + g;
#pragma unroll
            for (int ni = 0; ni < 4; ni++) {
                int col = wn + ni * 8 + 2 * t;
                if (row0 < N_NODES)
                    *(float2*)(outp + (size_t)row0 * HDIM + col) =
                        make_float2(acc[mi][ni][0], acc[mi][ni][1]);
                if (row0 + 8 < N_NODES)
                    *(float2*)(outp + (size_t)(row0 + 8) * HDIM + col) =
                        make_float2(acc[mi][ni][2], acc[mi][ni][3]);
            }
        }
        __syncthreads();
    }
}

// ---------------- degree histogram ----------------
__global__ void k_deg(const int* __restrict__ dst) {
    int i = blockIdx.x * blockDim.x + threadIdx.x;
    if (i < N_EDGES) atomicAdd(&g_deg[dst[i]], 1);
}

// ---------------- single-block exclusive scan over g_deg -> g_off ----------------
__global__ void k_scan() {
    __shared__ int sbuf[1024];
    __shared__ int s_carry;
    int tid = threadIdx.x;
    if (tid == 0) s_carry = 0;
    __syncthreads();
    const int CH = 8192;
    for (int base = 0; base < N_NODES; base += CH) {
        int idx0 = base + tid * 8;
        int v[8];
        int s = 0;
#pragma unroll
        for (int j = 0; j < 8; j++) {
            v[j] = (idx0 + j < N_NODES) ? g_deg[idx0 + j] : 0;
            s += v[j];
        }
        sbuf[tid] = s;
        __syncthreads();
        for (int off = 1; off < 1024; off <<= 1) {
            int t2 = (tid >= off) ? sbuf[tid - off] : 0;
            __syncthreads();
            sbuf[tid] += t2;
            __syncthreads();
        }
        int excl = s_carry + sbuf[tid] - s;
#pragma unroll
        for (int j = 0; j < 8; j++) {
            if (idx0 + j < N_NODES) g_off[idx0 + j] = excl;
            excl += v[j];
        }
        __syncthreads();
        if (tid == 1023) s_carry += sbuf[1023];
        __syncthreads();
    }
    if (tid == 0) g_off[N_NODES] = s_carry;
}

// ---------------- scatter edges into CSR-by-dst ----------------
__global__ void k_scatter(const int* __restrict__ src, const int* __restrict__ dst,
                          const int* __restrict__ rel) {
    int i = blockIdx.x * blockDim.x + threadIdx.x;
    if (i < N_EDGES) {
        int d = dst[i];
        int p = g_off[d] + atomicAdd(&g_cursor[d], 1);
        g_ekey[p] = (rel[i] << 16) | src[i];
    }
}

// ---------------- aggregation: warp per node; mean + self-loop + bias + relu ------
__global__ void k_aggregate(const float* __restrict__ bias, float* __restrict__ out) {
    int warp = (blockIdx.x * blockDim.x + threadIdx.x) >> 5;
    int lane = threadIdx.x & 31;
    if (warp >= N_NODES) return;
    int beg = g_off[warp], end = g_off[warp + 1];
    float4 acc = make_float4(0.f, 0.f, 0.f, 0.f);
    int e = beg;
    for (; e + 1 < end; e += 2) {
        int k0 = g_ekey[e], k1 = g_ekey[e + 1];
        const float4* p0 = (const float4*)(g_Hr + ((size_t)(k0 >> 16) * N_NODES + (k0 & 0xFFFF)) * HDIM);
        const float4* p1 = (const float4*)(g_Hr + ((size_t)(k1 >> 16) * N_NODES + (k1 & 0xFFFF)) * HDIM);
        float4 m0 = p0[lane];
        float4 m1 = p1[lane];
        acc.x += m0.x + m1.x; acc.y += m0.y + m1.y;
        acc.z += m0.z + m1.z; acc.w += m0.w + m1.w;
    }
    if (e < end) {
        int k0 = g_ekey[e];
        const float4* p0 = (const float4*)(g_Hr + ((size_t)(k0 >> 16) * N_NODES + (k0 & 0xFFFF)) * HDIM);
        float4 m0 = p0[lane];
        acc.x += m0.x; acc.y += m0.y; acc.z += m0.z; acc.w += m0.w;
    }
    float scale = (end > beg) ? (1.0f / (float)(end - beg)) : 0.0f;
    float4 s = ((const float4*)(g_self + (size_t)warp * HDIM))[lane];
    float4 b = ((const float4*)bias)[lane];
    float4 o;
    o.x = fmaxf(fmaf(acc.x, scale, s.x + b.x), 0.f);
    o.y = fmaxf(fmaf(acc.y, scale, s.y + b.y), 0.f);
    o.z = fmaxf(fmaf(acc.z, scale, s.z + b.z), 0.f);
    o.w = fmaxf(fmaf(acc.w, scale, s.w + b.w), 0.f);
    ((float4*)out)[(size_t)warp * 32 + lane] = o;
}

// ---------------- launch ----------------
extern "C" void kernel_launch(void* const* d_in, const int* in_sizes, int n_in,
                              void* d_out, int out_size) {
    const float* h      = (const float*)d_in[0];
    const float* W      = (const float*)d_in[1];
    const float* W_loop = (const float*)d_in[2];
    const float* bias   = (const float*)d_in[3];
    const int*   src    = (const int*)d_in[4];
    const int*   dst    = (const int*)d_in[5];
    const int*   rel    = (const int*)d_in[6];
    float* out = (float*)d_out;

    void* p_deg = nullptr;
    void* p_cur = nullptr;
    cudaGetSymbolAddress(&p_deg, g_deg);
    cudaGetSymbolAddress(&p_cur, g_cursor);
    cudaMemsetAsync(p_deg, 0, N_NODES * sizeof(int));
    cudaMemsetAsync(p_cur, 0, N_NODES * sizeof(int));

    cudaFuncSetAttribute(k_gemm_mma, cudaFuncAttributeMaxDynamicSharedMemorySize, SM_TOTAL);

    const int EB = (N_EDGES + 255) / 256;
    k_deg<<<EB, 256>>>(dst);
    k_scan<<<1, 1024>>>();
    k_scatter<<<EB, 256>>>(src, dst, rel);

    k_convB<<<(NMAT * 4096 + 255) / 256, 256>>>(W, W_loop);

    k_gemm_mma<<<M_TILES, 256, SM_TOTAL>>>(h);

    int agg_blocks = (N_NODES * 32 + 255) / 256;
    k_aggregate<<<agg_blocks, 256>>>(bias, out);
}

// round 6
// speedup vs baseline: 4.5847x; 1.7833x over previous
#include <cuda_runtime.h>
#include <cuda_fp16.h>
#include <cstdint>

#define N_NODES 50000
#define N_EDGES 800000
#define HDIM    128
#define N_RELS  24
#define M_TILES 391          /* ceil(50000/128) */
#define NMAT    25           /* 24 relations + self-loop */

// ---------------- scratch (device globals; no allocation allowed) ----------------
__device__ __half g_H16[(size_t)NMAT * N_NODES * HDIM];   // 320 MB (24 rels + self)
__device__ int   g_deg[N_NODES];
__device__ int   g_cursor[N_NODES];
__device__ int   g_off[N_NODES + 1];
__device__ int   g_ekey[N_EDGES];                         // (rel<<16)|src, grouped by dst

// W^T as fp16, (n,k) row-major per matrix (k contiguous)
__device__ __half g_Bh[(size_t)NMAT * HDIM * HDIM];       // 0.8 MB

// ---------------- smem layout for GEMM (padded rows: 272 B = 136 fp16) ----------
#define ROWB    272
#define TILE_B  (128 * ROWB)            /* 34816 bytes per 128x128 fp16 tile */
#define SA      0
#define SB_BASE TILE_B
#define SM_TOTAL (3 * TILE_B)           /* A + 2 B bufs = 104448 */

// ================= helpers =================
#define CP_COMMIT()  asm volatile("cp.async.commit_group;" ::: "memory")

__device__ __forceinline__ uint32_t smem_u32(const void* p) {
    uint32_t a;
    asm("{ .reg .u64 t; cvta.to.shared.u64 t, %1; cvt.u32.u64 %0, t; }" : "=r"(a) : "l"(p));
    return a;
}
__device__ __forceinline__ void cp16s(uint32_t dst_smem, const void* src) {
    asm volatile("cp.async.cg.shared.global [%0], [%1], 16;" :: "r"(dst_smem), "l"(src));
}
__device__ __forceinline__ void ldsm_x4(uint32_t& r0, uint32_t& r1, uint32_t& r2, uint32_t& r3,
                                        uint32_t addr) {
    asm volatile("ldmatrix.sync.aligned.m8n8.x4.shared.b16 {%0,%1,%2,%3}, [%4];"
                 : "=r"(r0), "=r"(r1), "=r"(r2), "=r"(r3) : "r"(addr));
}
__device__ __forceinline__ void mma16816(float* c, const uint32_t* a, const uint32_t* b) {
    asm volatile(
        "mma.sync.aligned.m16n8k16.row.col.f32.f16.f16.f32 "
        "{%0,%1,%2,%3}, {%4,%5,%6,%7}, {%8,%9}, {%0,%1,%2,%3};"
        : "+f"(c[0]), "+f"(c[1]), "+f"(c[2]), "+f"(c[3])
        : "r"(a[0]), "r"(a[1]), "r"(a[2]), "r"(a[3]), "r"(b[0]), "r"(b[1]));
}

// ---------------- conv B: g_Bh[r][n][k] = fp16(W[r][k][n]) ----------------------
__global__ void k_convB(const float* __restrict__ W, const float* __restrict__ W_loop) {
    int idx = blockIdx.x * blockDim.x + threadIdx.x;
    if (idx >= NMAT * 4096) return;
    int r = idx >> 12, q = idx & 4095;
    int n = q >> 5, c4 = q & 31;          // k = c4*4 .. c4*4+3
    const float* Wsrc = (r < N_RELS) ? (W + (size_t)r * HDIM * HDIM) : W_loop;
    float4 v;
    v.x = Wsrc[(size_t)(c4 * 4 + 0) * HDIM + n];
    v.y = Wsrc[(size_t)(c4 * 4 + 1) * HDIM + n];
    v.z = Wsrc[(size_t)(c4 * 4 + 2) * HDIM + n];
    v.w = Wsrc[(size_t)(c4 * 4 + 3) * HDIM + n];
    __half2 h0 = __floats2half2_rn(v.x, v.y);
    __half2 h1 = __floats2half2_rn(v.z, v.w);
    size_t off = (size_t)r * HDIM * HDIM + (size_t)n * HDIM + c4 * 4;
    *(uint2*)(g_Bh + off) = make_uint2(*(uint32_t*)&h0, *(uint32_t*)&h1);
}

// ---------------- GEMM via mma.sync fp16: CTA = one 128-row tile x 25 matrices ---
__global__ __launch_bounds__(256, 2) void k_gemm_f16(const float* __restrict__ h) {
    extern __shared__ char smem[];
    const uint32_t sbase = smem_u32(smem);
    const int tid = threadIdx.x;
    const int m0 = blockIdx.x * 128;

    // ---- prologue: load + convert A tile (fp32 -> fp16) into padded smem ----
    for (int q = tid; q < 4096; q += 256) {
        int row = q >> 5, c4 = q & 31;
        float4 v = make_float4(0.f, 0.f, 0.f, 0.f);
        int grow = m0 + row;
        if (grow < N_NODES) v = ((const float4*)(h + (size_t)grow * HDIM))[c4];
        __half2 h0 = __floats2half2_rn(v.x, v.y);
        __half2 h1 = __floats2half2_rn(v.z, v.w);
        *(uint2*)(smem + SA + row * ROWB + c4 * 8) = make_uint2(*(uint32_t*)&h0, *(uint32_t*)&h1);
    }

    // ---- B prefetch helper ----
    auto issue_B = [&](int r, int buf) {
        uint32_t bb = sbase + SB_BASE + buf * TILE_B;
        const char* gb = (const char*)g_Bh + (size_t)r * 32768;
        for (int q = tid; q < 2048; q += 256) {
            int row = q >> 4, seg = q & 15;
            cp16s(bb + row * ROWB + seg * 16, gb + row * 256 + seg * 16);
        }
    };

    issue_B(0, 0);
    CP_COMMIT();

    const int lane = tid & 31, wid = tid >> 5;
    const int g = lane >> 2, t = lane & 3;
    const int wm = (wid & 1) * 64;        // warp m offset
    const int wn = (wid >> 1) * 32;       // warp n offset

    // ldmatrix lane-address components
    const int a_row = wm + (lane & 15);          // + mi*16
    const int a_kb  = (lane & 16) ? 16 : 0;      // k-half byte offset
    const int b_n   = wn + ((lane >> 4) & 1) * 8 + (lane & 7);   // + nh*16 (covers ni, ni+1)
    const int b_kb  = (lane & 8) ? 16 : 0;

    for (int r = 0; r < NMAT; r++) {
        if (r + 1 < NMAT) {
            issue_B(r + 1, (r + 1) & 1);
            CP_COMMIT();
            asm volatile("cp.async.wait_group 1;" ::: "memory");
        } else {
            asm volatile("cp.async.wait_group 0;" ::: "memory");
        }
        __syncthreads();

        const uint32_t Ab = sbase + SA;
        const uint32_t Bb = sbase + SB_BASE + (r & 1) * TILE_B;

        float acc[4][4][4];
#pragma unroll
        for (int mi = 0; mi < 4; mi++)
#pragma unroll
            for (int ni = 0; ni < 4; ni++)
#pragma unroll
                for (int c = 0; c < 4; c++) acc[mi][ni][c] = 0.f;

#pragma unroll
        for (int ks = 0; ks < 8; ks++) {
            const int kb = ks * 32;
            uint32_t a[4][4];
#pragma unroll
            for (int mi = 0; mi < 4; mi++)
                ldsm_x4(a[mi][0], a[mi][1], a[mi][2], a[mi][3],
                        Ab + (a_row + mi * 16) * ROWB + kb + a_kb);
            uint32_t b[4][2];
#pragma unroll
            for (int nh = 0; nh < 2; nh++)
                ldsm_x4(b[nh * 2][0], b[nh * 2][1], b[nh * 2 + 1][0], b[nh * 2 + 1][1],
                        Bb + (b_n + nh * 16) * ROWB + kb + b_kb);
#pragma unroll
            for (int mi = 0; mi < 4; mi++)
#pragma unroll
                for (int ni = 0; ni < 4; ni++)
                    mma16816(acc[mi][ni], a[mi], b[ni]);
        }

        // ---- store D tile as fp16 ----
        __half* outp = g_H16 + (size_t)r * N_NODES * HDIM;
#pragma unroll
        for (int mi = 0; mi < 4; mi++) {
            int row0 = m0 + wm + mi * 16 + g;
#pragma unroll
            for (int ni = 0; ni < 4; ni++) {
                int col = wn + ni * 8 + 2 * t;
                if (row0 < N_NODES) {
                    __half2 p = __floats2half2_rn(acc[mi][ni][0], acc[mi][ni][1]);
                    *(uint32_t*)(outp + (size_t)row0 * HDIM + col) = *(uint32_t*)&p;
                }
                if (row0 + 8 < N_NODES) {
                    __half2 p = __floats2half2_rn(acc[mi][ni][2], acc[mi][ni][3]);
                    *(uint32_t*)(outp + (size_t)(row0 + 8) * HDIM + col) = *(uint32_t*)&p;
                }
            }
        }
        __syncthreads();
    }
}

// ---------------- degree histogram ----------------
__global__ void k_deg(const int* __restrict__ dst) {
    int i = blockIdx.x * blockDim.x + threadIdx.x;
    if (i < N_EDGES) atomicAdd(&g_deg[dst[i]], 1);
}

// ---------------- single-block exclusive scan over g_deg -> g_off ----------------
__global__ void k_scan() {
    __shared__ int sbuf[1024];
    __shared__ int s_carry;
    int tid = threadIdx.x;
    if (tid == 0) s_carry = 0;
    __syncthreads();
    const int CH = 8192;
    for (int base = 0; base < N_NODES; base += CH) {
        int idx0 = base + tid * 8;
        int v[8];
        int s = 0;
#pragma unroll
        for (int j = 0; j < 8; j++) {
            v[j] = (idx0 + j < N_NODES) ? g_deg[idx0 + j] : 0;
            s += v[j];
        }
        sbuf[tid] = s;
        __syncthreads();
        for (int off = 1; off < 1024; off <<= 1) {
            int t2 = (tid >= off) ? sbuf[tid - off] : 0;
            __syncthreads();
            sbuf[tid] += t2;
            __syncthreads();
        }
        int excl = s_carry + sbuf[tid] - s;
#pragma unroll
        for (int j = 0; j < 8; j++) {
            if (idx0 + j < N_NODES) g_off[idx0 + j] = excl;
            excl += v[j];
        }
        __syncthreads();
        if (tid == 1023) s_carry += sbuf[1023];
        __syncthreads();
    }
    if (tid == 0) g_off[N_NODES] = s_carry;
}

// ---------------- scatter edges into CSR-by-dst ----------------
__global__ void k_scatter(const int* __restrict__ src, const int* __restrict__ dst,
                          const int* __restrict__ rel) {
    int i = blockIdx.x * blockDim.x + threadIdx.x;
    if (i < N_EDGES) {
        int d = dst[i];
        int p = g_off[d] + atomicAdd(&g_cursor[d], 1);
        g_ekey[p] = (rel[i] << 16) | src[i];
    }
}

// ---------------- aggregation: warp per node; mean + self-loop + bias + relu ------
__device__ __forceinline__ void add4(float4& acc, uint2 u) {
    float2 lo = __half22float2(*(__half2*)&u.x);
    float2 hi = __half22float2(*(__half2*)&u.y);
    acc.x += lo.x; acc.y += lo.y; acc.z += hi.x; acc.w += hi.y;
}

__global__ void k_aggregate(const float* __restrict__ bias, float* __restrict__ out) {
    int warp = (blockIdx.x * blockDim.x + threadIdx.x) >> 5;
    int lane = threadIdx.x & 31;
    if (warp >= N_NODES) return;
    int beg = g_off[warp], end = g_off[warp + 1];
    float4 acc = make_float4(0.f, 0.f, 0.f, 0.f);
    int e = beg;
    for (; e + 1 < end; e += 2) {
        int k0 = g_ekey[e], k1 = g_ekey[e + 1];
        const uint2* p0 = (const uint2*)(g_H16 + ((size_t)(k0 >> 16) * N_NODES + (k0 & 0xFFFF)) * HDIM);
        const uint2* p1 = (const uint2*)(g_H16 + ((size_t)(k1 >> 16) * N_NODES + (k1 & 0xFFFF)) * HDIM);
        uint2 u0 = p0[lane];
        uint2 u1 = p1[lane];
        add4(acc, u0);
        add4(acc, u1);
    }
    if (e < end) {
        int k0 = g_ekey[e];
        const uint2* p0 = (const uint2*)(g_H16 + ((size_t)(k0 >> 16) * N_NODES + (k0 & 0xFFFF)) * HDIM);
        uint2 u0 = p0[lane];
        add4(acc, u0);
    }
    float scale = (end > beg) ? (1.0f / (float)(end - beg)) : 0.0f;
    // self-loop row (matrix index 24)
    uint2 su = ((const uint2*)(g_H16 + ((size_t)N_RELS * N_NODES + warp) * HDIM))[lane];
    float2 slo = __half22float2(*(__half2*)&su.x);
    float2 shi = __half22float2(*(__half2*)&su.y);
    float4 b = ((const float4*)bias)[lane];
    float4 o;
    o.x = fmaxf(fmaf(acc.x, scale, slo.x + b.x), 0.f);
    o.y = fmaxf(fmaf(acc.y, scale, slo.y + b.y), 0.f);
    o.z = fmaxf(fmaf(acc.z, scale, shi.x + b.z), 0.f);
    o.w = fmaxf(fmaf(acc.w, scale, shi.y + b.w), 0.f);
    ((float4*)out)[(size_t)warp * 32 + lane] = o;
}

// ---------------- launch ----------------
extern "C" void kernel_launch(void* const* d_in, const int* in_sizes, int n_in,
                              void* d_out, int out_size) {
    const float* h      = (const float*)d_in[0];
    const float* W      = (const float*)d_in[1];
    const float* W_loop = (const float*)d_in[2];
    const float* bias   = (const float*)d_in[3];
    const int*   src    = (const int*)d_in[4];
    const int*   dst    = (const int*)d_in[5];
    const int*   rel    = (const int*)d_in[6];
    float* out = (float*)d_out;

    void* p_deg = nullptr;
    void* p_cur = nullptr;
    cudaGetSymbolAddress(&p_deg, g_deg);
    cudaGetSymbolAddress(&p_cur, g_cursor);
    cudaMemsetAsync(p_deg, 0, N_NODES * sizeof(int));
    cudaMemsetAsync(p_cur, 0, N_NODES * sizeof(int));

    cudaFuncSetAttribute(k_gemm_f16, cudaFuncAttributeMaxDynamicSharedMemorySize, SM_TOTAL);

    const int EB = (N_EDGES + 255) / 256;
    k_deg<<<EB, 256>>>(dst);
    k_scan<<<1, 1024>>>();
    k_scatter<<<EB, 256>>>(src, dst, rel);

    k_convB<<<(NMAT * 4096 + 255) / 256, 256>>>(W, W_loop);

    k_gemm_f16<<<M_TILES, 256, SM_TOTAL>>>(h);

    int agg_blocks = (N_NODES * 32 + 255) / 256;
    k_aggregate<<<agg_blocks, 256>>>(bias, out);
}

// round 8
// speedup vs baseline: 4.7360x; 1.0330x over previous
#include <cuda_runtime.h>
#include <cuda_fp16.h>
#include <cstdint>

#define N_NODES 50000
#define N_EDGES 800000
#define HDIM    128
#define N_RELS  24
#define M_TILES 391          /* ceil(50000/128) */
#define NMAT    25           /* 24 relations + self-loop */
#define RCHUNK  5            /* rels per CTA */
#define NCHUNK  5            /* NMAT / RCHUNK */

// ---------------- scratch (device globals; no allocation allowed) ----------------
__device__ __half g_H16[(size_t)NMAT * N_NODES * HDIM];   // 320 MB (24 rels + self)
__device__ int   g_deg[N_NODES];
__device__ int   g_cursor[N_NODES];
__device__ int   g_off[N_NODES + 1];
__device__ int   g_ekey[N_EDGES];                         // (rel<<16)|src, grouped by dst

// W^T as fp16, (n,k) row-major per matrix (k contiguous)
__device__ __half g_Bh[(size_t)NMAT * HDIM * HDIM];       // 0.8 MB

// ---------------- smem layout for GEMM (padded rows: 272 B = 136 fp16) ----------
#define ROWB    272
#define TILE_B  (128 * ROWB)            /* 34816 bytes per 128x128 fp16 tile */
#define SA      0
#define SB_BASE TILE_B
#define SM_TOTAL (3 * TILE_B)           /* A + 2 B bufs = 104448 */

// ================= helpers =================
#define CP_COMMIT()  asm volatile("cp.async.commit_group;" ::: "memory")

__device__ __forceinline__ uint32_t smem_u32(const void* p) {
    uint32_t a;
    asm("{ .reg .u64 t; cvta.to.shared.u64 t, %1; cvt.u32.u64 %0, t; }" : "=r"(a) : "l"(p));
    return a;
}
__device__ __forceinline__ void cp16s(uint32_t dst_smem, const void* src) {
    asm volatile("cp.async.cg.shared.global [%0], [%1], 16;" :: "r"(dst_smem), "l"(src));
}
__device__ __forceinline__ void ldsm_x4(uint32_t& r0, uint32_t& r1, uint32_t& r2, uint32_t& r3,
                                        uint32_t addr) {
    asm volatile("ldmatrix.sync.aligned.m8n8.x4.shared.b16 {%0,%1,%2,%3}, [%4];"
                 : "=r"(r0), "=r"(r1), "=r"(r2), "=r"(r3) : "r"(addr));
}
__device__ __forceinline__ void mma16816(float* c, const uint32_t* a, const uint32_t* b) {
    asm volatile(
        "mma.sync.aligned.m16n8k16.row.col.f32.f16.f16.f32 "
        "{%0,%1,%2,%3}, {%4,%5,%6,%7}, {%8,%9}, {%0,%1,%2,%3};"
        : "+f"(c[0]), "+f"(c[1]), "+f"(c[2]), "+f"(c[3])
        : "r"(a[0]), "r"(a[1]), "r"(a[2]), "r"(a[3]), "r"(b[0]), "r"(b[1]));
}

// ---------------- conv B: g_Bh[r][n][k] = fp16(W[r][k][n]) ----------------------
__global__ void k_convB(const float* __restrict__ W, const float* __restrict__ W_loop) {
    int idx = blockIdx.x * blockDim.x + threadIdx.x;
    if (idx >= NMAT * 4096) return;
    int r = idx >> 12, q = idx & 4095;
    int n = q >> 5, c4 = q & 31;          // k = c4*4 .. c4*4+3
    const float* Wsrc = (r < N_RELS) ? (W + (size_t)r * HDIM * HDIM) : W_loop;
    float4 v;
    v.x = Wsrc[(size_t)(c4 * 4 + 0) * HDIM + n];
    v.y = Wsrc[(size_t)(c4 * 4 + 1) * HDIM + n];
    v.z = Wsrc[(size_t)(c4 * 4 + 2) * HDIM + n];
    v.w = Wsrc[(size_t)(c4 * 4 + 3) * HDIM + n];
    __half2 h0 = __floats2half2_rn(v.x, v.y);
    __half2 h1 = __floats2half2_rn(v.z, v.w);
    size_t off = (size_t)r * HDIM * HDIM + (size_t)n * HDIM + c4 * 4;
    *(uint2*)(g_Bh + off) = make_uint2(*(uint32_t*)&h0, *(uint32_t*)&h1);
}

// ---- GEMM via mma.sync fp16: CTA = one 128-row tile x RCHUNK matrices ----------
__global__ __launch_bounds__(256, 2) void k_gemm_f16(const float* __restrict__ h) {
    extern __shared__ char smem[];
    const uint32_t sbase = smem_u32(smem);
    const int tid = threadIdx.x;
    const int m0 = blockIdx.x * 128;
    const int r0 = blockIdx.y * RCHUNK;

    // ---- prologue: load + convert A tile (fp32 -> fp16) into padded smem ----
    for (int q = tid; q < 4096; q += 256) {
        int row = q >> 5, c4 = q & 31;
        float4 v = make_float4(0.f, 0.f, 0.f, 0.f);
        int grow = m0 + row;
        if (grow < N_NODES) v = ((const float4*)(h + (size_t)grow * HDIM))[c4];
        __half2 h0 = __floats2half2_rn(v.x, v.y);
        __half2 h1 = __floats2half2_rn(v.z, v.w);
        *(uint2*)(smem + SA + row * ROWB + c4 * 8) = make_uint2(*(uint32_t*)&h0, *(uint32_t*)&h1);
    }

    // ---- B prefetch helper ----
    auto issue_B = [&](int r, int buf) {
        uint32_t bb = sbase + SB_BASE + buf * TILE_B;
        const char* gb = (const char*)g_Bh + (size_t)r * 32768;
        for (int q = tid; q < 2048; q += 256) {
            int row = q >> 4, seg = q & 15;
            cp16s(bb + row * ROWB + seg * 16, gb + row * 256 + seg * 16);
        }
    };

    issue_B(r0, 0);
    CP_COMMIT();

    const int lane = tid & 31, wid = tid >> 5;
    const int g = lane >> 2, t = lane & 3;
    const int wm = (wid & 1) * 64;        // warp m offset
    const int wn = (wid >> 1) * 32;       // warp n offset

    // ldmatrix lane-address components
    const int a_row = wm + (lane & 15);          // + mi*16
    const int a_kb  = (lane & 16) ? 16 : 0;      // k-half byte offset
    const int b_n   = wn + ((lane >> 4) & 1) * 8 + (lane & 7);   // + nh*16
    const int b_kb  = (lane & 8) ? 16 : 0;

    for (int i = 0; i < RCHUNK; i++) {
        const int r = r0 + i;
        if (i + 1 < RCHUNK) {
            issue_B(r + 1, (i + 1) & 1);
            CP_COMMIT();
            asm volatile("cp.async.wait_group 1;" ::: "memory");
        } else {
            asm volatile("cp.async.wait_group 0;" ::: "memory");
        }
        __syncthreads();

        const uint32_t Ab = sbase + SA;
        const uint32_t Bb = sbase + SB_BASE + (i & 1) * TILE_B;

        float acc[4][4][4];
#pragma unroll
        for (int mi = 0; mi < 4; mi++)
#pragma unroll
            for (int ni = 0; ni < 4; ni++)
#pragma unroll
                for (int c = 0; c < 4; c++) acc[mi][ni][c] = 0.f;

#pragma unroll
        for (int ks = 0; ks < 8; ks++) {
            const int kb = ks * 32;
            uint32_t a[4][4];
#pragma unroll
            for (int mi = 0; mi < 4; mi++)
                ldsm_x4(a[mi][0], a[mi][1], a[mi][2], a[mi][3],
                        Ab + (a_row + mi * 16) * ROWB + kb + a_kb);
            uint32_t b[4][2];
#pragma unroll
            for (int nh = 0; nh < 2; nh++)
                ldsm_x4(b[nh * 2][0], b[nh * 2][1], b[nh * 2 + 1][0], b[nh * 2 + 1][1],
                        Bb + (b_n + nh * 16) * ROWB + kb + b_kb);
#pragma unroll
            for (int mi = 0; mi < 4; mi++)
#pragma unroll
                for (int ni = 0; ni < 4; ni++)
                    mma16816(acc[mi][ni], a[mi], b[ni]);
        }

        // ---- store D tile as fp16 ----
        __half* outp = g_H16 + (size_t)r * N_NODES * HDIM;
#pragma unroll
        for (int mi = 0; mi < 4; mi++) {
            int row0 = m0 + wm + mi * 16 + g;
#pragma unroll
            for (int ni = 0; ni < 4; ni++) {
                int col = wn + ni * 8 + 2 * t;
                if (row0 < N_NODES) {
                    __half2 p = __floats2half2_rn(acc[mi][ni][0], acc[mi][ni][1]);
                    *(uint32_t*)(outp + (size_t)row0 * HDIM + col) = *(uint32_t*)&p;
                }
                if (row0 + 8 < N_NODES) {
                    __half2 p = __floats2half2_rn(acc[mi][ni][2], acc[mi][ni][3]);
                    *(uint32_t*)(outp + (size_t)(row0 + 8) * HDIM + col) = *(uint32_t*)&p;
                }
            }
        }
        __syncthreads();
    }
}

// ---------------- degree histogram ----------------
__global__ void k_deg(const int* __restrict__ dst) {
    int i = blockIdx.x * blockDim.x + threadIdx.x;
    if (i < N_EDGES) atomicAdd(&g_deg[dst[i]], 1);
}

// ---------------- single-block exclusive scan over g_deg -> g_off ----------------
__global__ void k_scan() {
    __shared__ int sbuf[1024];
    __shared__ int s_carry;
    int tid = threadIdx.x;
    if (tid == 0) s_carry = 0;
    __syncthreads();
    const int CH = 8192;
    for (int base = 0; base < N_NODES; base += CH) {
        int idx0 = base + tid * 8;
        int v[8];
        int s = 0;
#pragma unroll
        for (int j = 0; j < 8; j++) {
            v[j] = (idx0 + j < N_NODES) ? g_deg[idx0 + j] : 0;
            s += v[j];
        }
        sbuf[tid] = s;
        __syncthreads();
        for (int off = 1; off < 1024; off <<= 1) {
            int t2 = (tid >= off) ? sbuf[tid - off] : 0;
            __syncthreads();
            sbuf[tid] += t2;
            __syncthreads();
        }
        int excl = s_carry + sbuf[tid] - s;
#pragma unroll
        for (int j = 0; j < 8; j++) {
            if (idx0 + j < N_NODES) g_off[idx0 + j] = excl;
            excl += v[j];
        }
        __syncthreads();
        if (tid == 1023) s_carry += sbuf[1023];
        __syncthreads();
    }
    if (tid == 0) g_off[N_NODES] = s_carry;
}

// ---------------- scatter edges into CSR-by-dst ----------------
__global__ void k_scatter(const int* __restrict__ src, const int* __restrict__ dst,
                          const int* __restrict__ rel) {
    int i = blockIdx.x * blockDim.x + threadIdx.x;
    if (i < N_EDGES) {
        int d = dst[i];
        int p = g_off[d] + atomicAdd(&g_cursor[d], 1);
        g_ekey[p] = (rel[i] << 16) | src[i];
    }
}

// ---------------- aggregation: warp per node; mean + self-loop + bias + relu ------
__device__ __forceinline__ void add4(float4& acc, uint2 u) {
    float2 lo = __half22float2(*(__half2*)&u.x);
    float2 hi = __half22float2(*(__half2*)&u.y);
    acc.x += lo.x; acc.y += lo.y; acc.z += hi.x; acc.w += hi.y;
}

__global__ void k_aggregate(const float* __restrict__ bias, float* __restrict__ out) {
    int warp = (blockIdx.x * blockDim.x + threadIdx.x) >> 5;
    int lane = threadIdx.x & 31;
    if (warp >= N_NODES) return;
    int beg = g_off[warp], end = g_off[warp + 1];
    float4 acc = make_float4(0.f, 0.f, 0.f, 0.f);
    int e = beg;
    for (; e + 1 < end; e += 2) {
        int k0 = g_ekey[e], k1 = g_ekey[e + 1];
        const uint2* p0 = (const uint2*)(g_H16 + ((size_t)(k0 >> 16) * N_NODES + (k0 & 0xFFFF)) * HDIM);
        const uint2* p1 = (const uint2*)(g_H16 + ((size_t)(k1 >> 16) * N_NODES + (k1 & 0xFFFF)) * HDIM);
        uint2 u0 = p0[lane];
        uint2 u1 = p1[lane];
        add4(acc, u0);
        add4(acc, u1);
    }
    if (e < end) {
        int k0 = g_ekey[e];
        const uint2* p0 = (const uint2*)(g_H16 + ((size_t)(k0 >> 16) * N_NODES + (k0 & 0xFFFF)) * HDIM);
        uint2 u0 = p0[lane];
        add4(acc, u0);
    }
    float scale = (end > beg) ? (1.0f / (float)(end - beg)) : 0.0f;
    // self-loop row (matrix index 24)
    uint2 su = ((const uint2*)(g_H16 + ((size_t)N_RELS * N_NODES + warp) * HDIM))[lane];
    float2 slo = __half22float2(*(__half2*)&su.x);
    float2 shi = __half22float2(*(__half2*)&su.y);
    float4 b = ((const float4*)bias)[lane];
    float4 o;
    o.x = fmaxf(fmaf(acc.x, scale, slo.x + b.x), 0.f);
    o.y = fmaxf(fmaf(acc.y, scale, slo.y + b.y), 0.f);
    o.z = fmaxf(fmaf(acc.z, scale, shi.x + b.z), 0.f);
    o.w = fmaxf(fmaf(acc.w, scale, shi.y + b.w), 0.f);
    ((float4*)out)[(size_t)warp * 32 + lane] = o;
}

// ---------------- launch ----------------
extern "C" void kernel_launch(void* const* d_in, const int* in_sizes, int n_in,
                              void* d_out, int out_size) {
    const float* h      = (const float*)d_in[0];
    const float* W      = (const float*)d_in[1];
    const float* W_loop = (const float*)d_in[2];
    const float* bias   = (const float*)d_in[3];
    const int*   src    = (const int*)d_in[4];
    const int*   dst    = (const int*)d_in[5];
    const int*   rel    = (const int*)d_in[6];
    float* out = (float*)d_out;

    void* p_deg = nullptr;
    void* p_cur = nullptr;
    cudaGetSymbolAddress(&p_deg, g_deg);
    cudaGetSymbolAddress(&p_cur, g_cursor);
    cudaMemsetAsync(p_deg, 0, N_NODES * sizeof(int));
    cudaMemsetAsync(p_cur, 0, N_NODES * sizeof(int));

    cudaFuncSetAttribute(k_gemm_f16, cudaFuncAttributeMaxDynamicSharedMemorySize, SM_TOTAL);

    const int EB = (N_EDGES + 255) / 256;
    k_deg<<<EB, 256>>>(dst);
    k_scan<<<1, 1024>>>();
    k_scatter<<<EB, 256>>>(src, dst, rel);

    k_convB<<<(NMAT * 4096 + 255) / 256, 256>>>(W, W_loop);

    dim3 ggrid(M_TILES, NCHUNK);
    k_gemm_f16<<<ggrid, 256, SM_TOTAL>>>(h);

    int agg_blocks = (N_NODES * 32 + 255) / 256;
    k_aggregate<<<agg_blocks, 256>>>(bias, out);
}